// round 5
// baseline (speedup 1.0000x reference)
#include <cuda_runtime.h>
#include <cstdint>
#include <cstddef>

#define NMAX 100000
#define EMAX 1700000

// ---------------- scratch (device globals; no allocations allowed) ----------
__device__ float g_H[(size_t)NMAX * 64];
__device__ float g_G[(size_t)NMAX * 64];
__device__ float g_A[(size_t)NMAX * 64];
__device__ float g_dinv[NMAX];
__device__ int   g_deg[NMAX];
__device__ int   g_fill[NMAX];
__device__ int   g_rowptr[NMAX + 1];
__device__ int   g_bsum[1024];
__device__ int   g_csr[EMAX];
__device__ int   g_is64;

typedef unsigned long long ull;

// f32x2 packed FMA (sm_100+): d = a*b + d, lanewise on 2 packed fp32
__device__ __forceinline__ void fma2(ull& d, ull a, ull b) {
    asm("fma.rn.f32x2 %0, %1, %2, %0;" : "+l"(d) : "l"(a), "l"(b));
}
__device__ __forceinline__ float2 unpk(ull a) {
    float2 v;
    asm("mov.b64 {%0, %1}, %2;" : "=f"(v.x), "=f"(v.y) : "l"(a));
    return v;
}

// ---------------- zero + edge dtype detection --------------------------------
__global__ void zero_k(const int* __restrict__ ei, int n) {
    int i = blockIdx.x * 256 + threadIdx.x;
    if (i < n) { g_deg[i] = 0; g_fill[i] = 0; }
    if (blockIdx.x == 0 && threadIdx.x == 0) {
        // int64 little-endian, values < 2^31 => odd 32-bit words all zero
        int ok = 1;
        for (int j = 0; j < 64; j++)
            if (ei[2 * j + 1] != 0) { ok = 0; break; }
        g_is64 = ok;
    }
}

// ---------------- CSR build --------------------------------------------------
__global__ void deg_accum_k(const int* __restrict__ ei, int E) {
    int e = blockIdx.x * 256 + threadIdx.x;
    if (e >= E) return;
    int d;
    if (g_is64) d = ((const int2*)ei)[(size_t)E + e].x;
    else        d = ei[(size_t)E + e];
    atomicAdd(&g_deg[d], 1);
}

__global__ void scan1_k(int n) {
    __shared__ int s[256];
    int tx = threadIdx.x;
    int i = blockIdx.x * 256 + tx;
    int v = (i < n) ? g_deg[i] : 0;
    s[tx] = v;
    __syncthreads();
#pragma unroll
    for (int o = 1; o < 256; o <<= 1) {
        int t = 0;
        if (tx >= o) t = s[tx - o];
        __syncthreads();
        if (tx >= o) s[tx] += t;
        __syncthreads();
    }
    if (i < n) g_rowptr[i] = s[tx] - v;
    if (tx == 255) g_bsum[blockIdx.x] = s[255];
}

// merged: block-offset scan (redundant per block) + apply + dinv
__global__ void scan23_k(int n, int nb, int E) {
    __shared__ int s[512];
    int tx = threadIdx.x;
    int v = (tx < nb) ? g_bsum[tx] : 0;
    s[tx] = v;
    __syncthreads();
#pragma unroll
    for (int o = 1; o < 512; o <<= 1) {
        int t = 0;
        if (tx >= o) t = s[tx - o];
        __syncthreads();
        if (tx >= o) s[tx] += t;
        __syncthreads();
    }
    int prefix = (blockIdx.x == 0) ? 0 : s[blockIdx.x - 1];   // inclusive scan -> excl
    if (tx < 256) {
        int i = blockIdx.x * 256 + tx;
        if (i < n) {
            g_rowptr[i] += prefix;
            g_dinv[i] = rsqrtf((float)(g_deg[i] + 1));
        }
    }
    if (blockIdx.x == 0 && tx == 0) g_rowptr[n] = E;
}

__global__ void fill_k(const int* __restrict__ ei, int E) {
    int e = blockIdx.x * 256 + threadIdx.x;
    if (e >= E) return;
    int s, d;
    if (g_is64) {
        s = ((const int2*)ei)[e].x;
        d = ((const int2*)ei)[(size_t)E + e].x;
    } else {
        s = ei[e];
        d = ei[(size_t)E + e];
    }
    int pos = g_rowptr[d] + atomicAdd(&g_fill[d], 1);
    g_csr[pos] = s;
}

// ---------------- GEMM with f32x2 FMA, pre-duplicated X ----------------------
// 128 threads/block. RPT rows x 8 cols per thread; ROWS = 128 for all shapes.
// X stored duplicated in smem ({x,x} pairs) so the inner loop needs no packing.
// XOR swizzle by (r>>3) over 16-byte blocks keeps LDS/STS conflict-free.
template <int FIN, int FOUT, bool INTR, bool CONV>
__global__ void __launch_bounds__(128) gemm_k(
    const float* __restrict__ in, const float* __restrict__ W,
    const float* __restrict__ bprev, const float* __restrict__ bout,
    float* __restrict__ out, int n)
{
    constexpr int CG   = FOUT / 8;        // col groups: 8 or 4
    constexpr int RG   = 128 / CG;        // row groups: 16 or 32
    constexpr int RPT  = 128 / RG;        // rows per thread: 8 or 4
    constexpr int ROWS = 128;
    constexpr int KC   = 32;
    constexpr int NC4  = KC / 4;          // input float4 blocks per row (8)
    constexpr int NB   = 2 * NC4;         // duplicated 16B blocks per row (16)

    __shared__ float Xs[ROWS * 2 * KC];   // duplicated: 32 KB
    __shared__ float Ws[KC * FOUT];

    const int tid = threadIdx.x;
    const int r0b = blockIdx.x * ROWS;
    const int rg  = tid / CG;
    const int cg  = tid % CG;
    const int r0  = rg * RPT;
    const int c0  = cg * 8;

    ull acc[RPT][4];
#pragma unroll
    for (int i = 0; i < RPT; i++)
#pragma unroll
        for (int j = 0; j < 4; j++) acc[i][j] = 0ull;

    for (int k0 = 0; k0 < FIN; k0 += KC) {
        // ---- load X tile [ROWS x KC], store duplicated + swizzled ----
        for (int idx = tid; idx < ROWS * NC4; idx += 128) {
            int r  = idx / NC4;
            int c4 = idx % NC4;
            int row = r0b + r;
            int col = k0 + c4 * 4;
            float4 v = make_float4(0.f, 0.f, 0.f, 0.f);
            if (row < n) {
                v = *(const float4*)(in + (size_t)row * FIN + col);
                if (INTR) {
                    float di = g_dinv[row];
                    v.x = fmaxf(fmaf(v.x, di, bprev[col + 0]), 0.f);
                    v.y = fmaxf(fmaf(v.y, di, bprev[col + 1]), 0.f);
                    v.z = fmaxf(fmaf(v.z, di, bprev[col + 2]), 0.f);
                    v.w = fmaxf(fmaf(v.w, di, bprev[col + 3]), 0.f);
                }
            }
            int key = (r >> 3) & (NB - 1);
            int b0 = (2 * c4)     ^ key;
            int b1 = (2 * c4 + 1) ^ key;
            ((float4*)Xs)[r * NB + b0] = make_float4(v.x, v.x, v.y, v.y);
            ((float4*)Xs)[r * NB + b1] = make_float4(v.z, v.z, v.w, v.w);
        }
        // ---- load W chunk [KC x FOUT] ----
        for (int idx = tid; idx < KC * FOUT / 4; idx += 128)
            ((float4*)Ws)[idx] = ((const float4*)(W + (size_t)k0 * FOUT))[idx];
        __syncthreads();

        // ---- inner loop: 4 k per step ----
#pragma unroll
        for (int kk = 0; kk < KC; kk += 4) {
            ulonglong2 w[4][2];
#pragma unroll
            for (int kj = 0; kj < 4; kj++) {
                const float* wr = Ws + (kk + kj) * FOUT + c0;
                w[kj][0] = *(const ulonglong2*)(wr);
                w[kj][1] = *(const ulonglong2*)(wr + 4);
            }
#pragma unroll
            for (int i = 0; i < RPT; i++) {
                int r = r0 + i;
                int key = (r >> 3) & (NB - 1);
                int bA = ((kk >> 1))     ^ key;
                int bB = ((kk >> 1) + 1) ^ key;
                ulonglong2 pA = ((const ulonglong2*)Xs)[r * NB + bA]; // {x0,x0},{x1,x1}
                ulonglong2 pB = ((const ulonglong2*)Xs)[r * NB + bB]; // {x2,x2},{x3,x3}
                fma2(acc[i][0], pA.x, w[0][0].x);
                fma2(acc[i][1], pA.x, w[0][0].y);
                fma2(acc[i][2], pA.x, w[0][1].x);
                fma2(acc[i][3], pA.x, w[0][1].y);
                fma2(acc[i][0], pA.y, w[1][0].x);
                fma2(acc[i][1], pA.y, w[1][0].y);
                fma2(acc[i][2], pA.y, w[1][1].x);
                fma2(acc[i][3], pA.y, w[1][1].y);
                fma2(acc[i][0], pB.x, w[2][0].x);
                fma2(acc[i][1], pB.x, w[2][0].y);
                fma2(acc[i][2], pB.x, w[2][1].x);
                fma2(acc[i][3], pB.x, w[2][1].y);
                fma2(acc[i][0], pB.y, w[3][0].x);
                fma2(acc[i][1], pB.y, w[3][0].y);
                fma2(acc[i][2], pB.y, w[3][1].x);
                fma2(acc[i][3], pB.y, w[3][1].y);
            }
        }
        __syncthreads();
    }

    // ---- epilogue ----
#pragma unroll
    for (int i = 0; i < RPT; i++) {
        int row = r0b + r0 + i;
        if (row < n) {
            float v[8];
#pragma unroll
            for (int j = 0; j < 4; j++) {
                float2 p = unpk(acc[i][j]);
                v[2 * j] = p.x; v[2 * j + 1] = p.y;
            }
            if (CONV) {
                float di = g_dinv[row];
#pragma unroll
                for (int j = 0; j < 8; j++) v[j] *= di;
            } else {
#pragma unroll
                for (int j = 0; j < 8; j++) v[j] += bout[c0 + j];
            }
            float* o = out + (size_t)row * FOUT + c0;
            *(float4*)(o)     = make_float4(v[0], v[1], v[2], v[3]);
            *(float4*)(o + 4) = make_float4(v[4], v[5], v[6], v[7]);
        }
    }
}

// ---------------- gather (64 cols): A[dst] = G[dst] + sum G[src] -------------
__global__ void gather64_k(const float* __restrict__ G, float* __restrict__ A, int n)
{
    int row  = blockIdx.x * 8 + (threadIdx.x >> 5);
    int lane = threadIdx.x & 31;
    if (row >= n) return;                        // warp-uniform exit
    const float2* G2 = (const float2*)G;
    int beg = g_rowptr[row], end = g_rowptr[row + 1];
    float2 aA = G2[(size_t)row * 32 + lane];     // self-loop term
    float2 aB = make_float2(0.f, 0.f);
    for (int p = beg; p < end; p += 32) {
        int m = end - p;
        if (m > 32) m = 32;
        int id = (lane < m) ? g_csr[p + lane] : 0;
        int j = 0;
#pragma unroll 4
        for (; j + 1 < m; j += 2) {
            int s0 = __shfl_sync(0xffffffffu, id, j);
            int s1 = __shfl_sync(0xffffffffu, id, j + 1);
            float2 v0 = G2[(size_t)s0 * 32 + lane];
            float2 v1 = G2[(size_t)s1 * 32 + lane];
            aA.x += v0.x; aA.y += v0.y;
            aB.x += v1.x; aB.y += v1.y;
        }
        if (j < m) {
            int s0 = __shfl_sync(0xffffffffu, id, j);
            float2 v0 = G2[(size_t)s0 * 32 + lane];
            aA.x += v0.x; aA.y += v0.y;
        }
    }
    ((float2*)A)[(size_t)row * 32 + lane] = make_float2(aA.x + aB.x, aA.y + aB.y);
}

// ---------------- fused gather (32 cols) + L2 normalize ----------------------
__global__ void gather_final_k(const float* __restrict__ G, const float* __restrict__ b3,
                               float* __restrict__ out, int n)
{
    int row  = blockIdx.x * 8 + (threadIdx.x >> 5);
    int lane = threadIdx.x & 31;
    if (row >= n) return;
    int beg = g_rowptr[row], end = g_rowptr[row + 1];
    float aA = G[(size_t)row * 32 + lane];
    float aB = 0.f;
    for (int p = beg; p < end; p += 32) {
        int m = end - p;
        if (m > 32) m = 32;
        int id = (lane < m) ? g_csr[p + lane] : 0;
        int j = 0;
#pragma unroll 4
        for (; j + 1 < m; j += 2) {
            int s0 = __shfl_sync(0xffffffffu, id, j);
            int s1 = __shfl_sync(0xffffffffu, id, j + 1);
            aA += G[(size_t)s0 * 32 + lane];
            aB += G[(size_t)s1 * 32 + lane];
        }
        if (j < m) {
            int s0 = __shfl_sync(0xffffffffu, id, j);
            aA += G[(size_t)s0 * 32 + lane];
        }
    }
    float v = (aA + aB) * g_dinv[row] + b3[lane];
    float ss = v * v;
#pragma unroll
    for (int o = 16; o; o >>= 1) ss += __shfl_xor_sync(0xffffffffu, ss, o);
    float nrm = sqrtf(ss);
    out[(size_t)row * 32 + lane] = v / fmaxf(nrm, 1e-12f);
}

// ---------------- launcher ---------------------------------------------------
extern "C" void kernel_launch(void* const* d_in, const int* in_sizes, int n_in,
                              void* d_out, int out_size)
{
    const float* x     = (const float*)d_in[0];
    const int*   ei    = (const int*)  d_in[1];
    const float* W_pre = (const float*)d_in[2];
    const float* b_pre = (const float*)d_in[3];
    const float* W1    = (const float*)d_in[4];
    const float* b1    = (const float*)d_in[5];
    const float* W2    = (const float*)d_in[6];
    const float* b2    = (const float*)d_in[7];
    const float* W3    = (const float*)d_in[8];
    const float* b3    = (const float*)d_in[9];
    float* out = (float*)d_out;

    const int n = in_sizes[0] / 128;
    const int E = in_sizes[1] / 2;

    float *pH, *pG, *pA;
    cudaGetSymbolAddress((void**)&pH, g_H);
    cudaGetSymbolAddress((void**)&pG, g_G);
    cudaGetSymbolAddress((void**)&pA, g_A);

    const int nb  = (n + 255) / 256;
    const int eb  = (E + 255) / 256;
    const int gb  = (n + 127) / 128;   // ROWS=128 for all GEMM shapes
    const int wb  = (n + 7) / 8;

    // ---- CSR build (reused by all 3 convs) ----
    zero_k<<<nb, 256>>>(ei, n);
    deg_accum_k<<<eb, 256>>>(ei, E);
    scan1_k<<<nb, 256>>>(n);
    scan23_k<<<nb, 512>>>(n, nb, E);
    fill_k<<<eb, 256>>>(ei, E);

    // ---- network ----
    gemm_k<128, 64, false, false><<<gb, 128>>>(x, W_pre, nullptr, b_pre, pH, n);

    gemm_k<64, 64, false, true><<<gb, 128>>>(pH, W1, nullptr, nullptr, pG, n);
    gather64_k<<<wb, 256>>>(pG, pA, n);

    gemm_k<64, 64, true, true><<<gb, 128>>>(pA, W2, b1, nullptr, pG, n);
    gather64_k<<<wb, 256>>>(pG, pA, n);

    gemm_k<64, 32, true, true><<<gb, 128>>>(pA, W3, b2, nullptr, pG, n);
    gather_final_k<<<wb, 256>>>(pG, b3, out, n);
}

// round 6
// speedup vs baseline: 1.0001x; 1.0001x over previous
#include <cuda_runtime.h>
#include <cstdint>
#include <cstddef>

#define NMAX 100000
#define EMAX 1700000

// ---------------- scratch (device globals; no allocations allowed) ----------
__device__ float g_H[(size_t)NMAX * 64];
__device__ float g_G[(size_t)NMAX * 64];
__device__ float g_A[(size_t)NMAX * 64];
__device__ float g_dinv[NMAX];
__device__ int   g_deg[NMAX];
__device__ int   g_fill[NMAX];
__device__ int   g_rowptr[NMAX + 1];
__device__ int   g_bsum[1024];
__device__ int   g_csr[EMAX];
__device__ int   g_is64;

typedef unsigned long long ull;

// f32x2 packed FMA (sm_100+): d = a*b + d, lanewise on 2 packed fp32
__device__ __forceinline__ void fma2(ull& d, ull a, ull b) {
    asm("fma.rn.f32x2 %0, %1, %2, %0;" : "+l"(d) : "l"(a), "l"(b));
}
__device__ __forceinline__ float2 unpk(ull a) {
    float2 v;
    asm("mov.b64 {%0, %1}, %2;" : "=f"(v.x), "=f"(v.y) : "l"(a));
    return v;
}

// ---------------- zero + edge dtype detection --------------------------------
__global__ void zero_k(const int* __restrict__ ei, int n) {
    int i = blockIdx.x * 256 + threadIdx.x;
    if (i < n) { g_deg[i] = 0; g_fill[i] = 0; }
    if (blockIdx.x == 0 && threadIdx.x == 0) {
        // int64 little-endian, values < 2^31 => odd 32-bit words all zero
        int ok = 1;
        for (int j = 0; j < 64; j++)
            if (ei[2 * j + 1] != 0) { ok = 0; break; }
        g_is64 = ok;
    }
}

// ---------------- CSR build --------------------------------------------------
__global__ void deg_accum_k(const int* __restrict__ ei, int E) {
    int e = blockIdx.x * 256 + threadIdx.x;
    if (e >= E) return;
    int d;
    if (g_is64) d = ((const int2*)ei)[(size_t)E + e].x;
    else        d = ei[(size_t)E + e];
    atomicAdd(&g_deg[d], 1);
}

__global__ void scan1_k(int n) {
    __shared__ int s[256];
    int tx = threadIdx.x;
    int i = blockIdx.x * 256 + tx;
    int v = (i < n) ? g_deg[i] : 0;
    s[tx] = v;
    __syncthreads();
#pragma unroll
    for (int o = 1; o < 256; o <<= 1) {
        int t = 0;
        if (tx >= o) t = s[tx - o];
        __syncthreads();
        if (tx >= o) s[tx] += t;
        __syncthreads();
    }
    if (i < n) g_rowptr[i] = s[tx] - v;
    if (tx == 255) g_bsum[blockIdx.x] = s[255];
}

// merged: block-offset scan (redundant per block) + apply + dinv
__global__ void scan23_k(int n, int nb, int E) {
    __shared__ int s[512];
    int tx = threadIdx.x;
    int v = (tx < nb) ? g_bsum[tx] : 0;
    s[tx] = v;
    __syncthreads();
#pragma unroll
    for (int o = 1; o < 512; o <<= 1) {
        int t = 0;
        if (tx >= o) t = s[tx - o];
        __syncthreads();
        if (tx >= o) s[tx] += t;
        __syncthreads();
    }
    int prefix = (blockIdx.x == 0) ? 0 : s[blockIdx.x - 1];   // inclusive scan -> excl
    if (tx < 256) {
        int i = blockIdx.x * 256 + tx;
        if (i < n) {
            g_rowptr[i] += prefix;
            g_dinv[i] = rsqrtf((float)(g_deg[i] + 1));
        }
    }
    if (blockIdx.x == 0 && tx == 0) g_rowptr[n] = E;
}

__global__ void fill_k(const int* __restrict__ ei, int E) {
    int e = blockIdx.x * 256 + threadIdx.x;
    if (e >= E) return;
    int s, d;
    if (g_is64) {
        s = ((const int2*)ei)[e].x;
        d = ((const int2*)ei)[(size_t)E + e].x;
    } else {
        s = ei[e];
        d = ei[(size_t)E + e];
    }
    int pos = g_rowptr[d] + atomicAdd(&g_fill[d], 1);
    g_csr[pos] = s;
}

// ---------------- GEMM with f32x2 FMA, pre-duplicated X ----------------------
// 128 threads/block. RPT rows x 8 cols per thread; ROWS = 128 for all shapes.
// X stored duplicated in smem ({x,x} pairs) so the inner loop needs no packing.
// XOR swizzle by (r>>3) over 16-byte blocks keeps LDS/STS conflict-free.
template <int FIN, int FOUT, bool INTR, bool CONV>
__global__ void __launch_bounds__(128) gemm_k(
    const float* __restrict__ in, const float* __restrict__ W,
    const float* __restrict__ bprev, const float* __restrict__ bout,
    float* __restrict__ out, int n)
{
    constexpr int CG   = FOUT / 8;        // col groups: 8 or 4
    constexpr int RG   = 128 / CG;        // row groups: 16 or 32
    constexpr int RPT  = 128 / RG;        // rows per thread: 8 or 4
    constexpr int ROWS = 128;
    constexpr int KC   = 32;
    constexpr int NC4  = KC / 4;          // input float4 blocks per row (8)
    constexpr int NB   = 2 * NC4;         // duplicated 16B blocks per row (16)

    __shared__ float Xs[ROWS * 2 * KC];   // duplicated: 32 KB
    __shared__ float Ws[KC * FOUT];

    const int tid = threadIdx.x;
    const int r0b = blockIdx.x * ROWS;
    const int rg  = tid / CG;
    const int cg  = tid % CG;
    const int r0  = rg * RPT;
    const int c0  = cg * 8;

    ull acc[RPT][4];
#pragma unroll
    for (int i = 0; i < RPT; i++)
#pragma unroll
        for (int j = 0; j < 4; j++) acc[i][j] = 0ull;

    for (int k0 = 0; k0 < FIN; k0 += KC) {
        // ---- load X tile [ROWS x KC], store duplicated + swizzled ----
        for (int idx = tid; idx < ROWS * NC4; idx += 128) {
            int r  = idx / NC4;
            int c4 = idx % NC4;
            int row = r0b + r;
            int col = k0 + c4 * 4;
            float4 v = make_float4(0.f, 0.f, 0.f, 0.f);
            if (row < n) {
                v = *(const float4*)(in + (size_t)row * FIN + col);
                if (INTR) {
                    float di = g_dinv[row];
                    v.x = fmaxf(fmaf(v.x, di, bprev[col + 0]), 0.f);
                    v.y = fmaxf(fmaf(v.y, di, bprev[col + 1]), 0.f);
                    v.z = fmaxf(fmaf(v.z, di, bprev[col + 2]), 0.f);
                    v.w = fmaxf(fmaf(v.w, di, bprev[col + 3]), 0.f);
                }
            }
            int key = (r >> 3) & (NB - 1);
            int b0 = (2 * c4)     ^ key;
            int b1 = (2 * c4 + 1) ^ key;
            ((float4*)Xs)[r * NB + b0] = make_float4(v.x, v.x, v.y, v.y);
            ((float4*)Xs)[r * NB + b1] = make_float4(v.z, v.z, v.w, v.w);
        }
        // ---- load W chunk [KC x FOUT] ----
        for (int idx = tid; idx < KC * FOUT / 4; idx += 128)
            ((float4*)Ws)[idx] = ((const float4*)(W + (size_t)k0 * FOUT))[idx];
        __syncthreads();

        // ---- inner loop: 4 k per step ----
#pragma unroll
        for (int kk = 0; kk < KC; kk += 4) {
            ulonglong2 w[4][2];
#pragma unroll
            for (int kj = 0; kj < 4; kj++) {
                const float* wr = Ws + (kk + kj) * FOUT + c0;
                w[kj][0] = *(const ulonglong2*)(wr);
                w[kj][1] = *(const ulonglong2*)(wr + 4);
            }
#pragma unroll
            for (int i = 0; i < RPT; i++) {
                int r = r0 + i;
                int key = (r >> 3) & (NB - 1);
                int bA = ((kk >> 1))     ^ key;
                int bB = ((kk >> 1) + 1) ^ key;
                ulonglong2 pA = ((const ulonglong2*)Xs)[r * NB + bA]; // {x0,x0},{x1,x1}
                ulonglong2 pB = ((const ulonglong2*)Xs)[r * NB + bB]; // {x2,x2},{x3,x3}
                fma2(acc[i][0], pA.x, w[0][0].x);
                fma2(acc[i][1], pA.x, w[0][0].y);
                fma2(acc[i][2], pA.x, w[0][1].x);
                fma2(acc[i][3], pA.x, w[0][1].y);
                fma2(acc[i][0], pA.y, w[1][0].x);
                fma2(acc[i][1], pA.y, w[1][0].y);
                fma2(acc[i][2], pA.y, w[1][1].x);
                fma2(acc[i][3], pA.y, w[1][1].y);
                fma2(acc[i][0], pB.x, w[2][0].x);
                fma2(acc[i][1], pB.x, w[2][0].y);
                fma2(acc[i][2], pB.x, w[2][1].x);
                fma2(acc[i][3], pB.x, w[2][1].y);
                fma2(acc[i][0], pB.y, w[3][0].x);
                fma2(acc[i][1], pB.y, w[3][0].y);
                fma2(acc[i][2], pB.y, w[3][1].x);
                fma2(acc[i][3], pB.y, w[3][1].y);
            }
        }
        __syncthreads();
    }

    // ---- epilogue ----
#pragma unroll
    for (int i = 0; i < RPT; i++) {
        int row = r0b + r0 + i;
        if (row < n) {
            float v[8];
#pragma unroll
            for (int j = 0; j < 4; j++) {
                float2 p = unpk(acc[i][j]);
                v[2 * j] = p.x; v[2 * j + 1] = p.y;
            }
            if (CONV) {
                float di = g_dinv[row];
#pragma unroll
                for (int j = 0; j < 8; j++) v[j] *= di;
            } else {
#pragma unroll
                for (int j = 0; j < 8; j++) v[j] += bout[c0 + j];
            }
            float* o = out + (size_t)row * FOUT + c0;
            *(float4*)(o)     = make_float4(v[0], v[1], v[2], v[3]);
            *(float4*)(o + 4) = make_float4(v[4], v[5], v[6], v[7]);
        }
    }
}

// ---------------- gather (64 cols): A[dst] = G[dst] + sum G[src] -------------
__global__ void gather64_k(const float* __restrict__ G, float* __restrict__ A, int n)
{
    int row  = blockIdx.x * 8 + (threadIdx.x >> 5);
    int lane = threadIdx.x & 31;
    if (row >= n) return;                        // warp-uniform exit
    const float2* G2 = (const float2*)G;
    int beg = g_rowptr[row], end = g_rowptr[row + 1];
    float2 aA = G2[(size_t)row * 32 + lane];     // self-loop term
    float2 aB = make_float2(0.f, 0.f);
    for (int p = beg; p < end; p += 32) {
        int m = end - p;
        if (m > 32) m = 32;
        int id = (lane < m) ? g_csr[p + lane] : 0;
        int j = 0;
#pragma unroll 4
        for (; j + 1 < m; j += 2) {
            int s0 = __shfl_sync(0xffffffffu, id, j);
            int s1 = __shfl_sync(0xffffffffu, id, j + 1);
            float2 v0 = G2[(size_t)s0 * 32 + lane];
            float2 v1 = G2[(size_t)s1 * 32 + lane];
            aA.x += v0.x; aA.y += v0.y;
            aB.x += v1.x; aB.y += v1.y;
        }
        if (j < m) {
            int s0 = __shfl_sync(0xffffffffu, id, j);
            float2 v0 = G2[(size_t)s0 * 32 + lane];
            aA.x += v0.x; aA.y += v0.y;
        }
    }
    ((float2*)A)[(size_t)row * 32 + lane] = make_float2(aA.x + aB.x, aA.y + aB.y);
}

// ---------------- fused gather (32 cols) + L2 normalize ----------------------
__global__ void gather_final_k(const float* __restrict__ G, const float* __restrict__ b3,
                               float* __restrict__ out, int n)
{
    int row  = blockIdx.x * 8 + (threadIdx.x >> 5);
    int lane = threadIdx.x & 31;
    if (row >= n) return;
    int beg = g_rowptr[row], end = g_rowptr[row + 1];
    float aA = G[(size_t)row * 32 + lane];
    float aB = 0.f;
    for (int p = beg; p < end; p += 32) {
        int m = end - p;
        if (m > 32) m = 32;
        int id = (lane < m) ? g_csr[p + lane] : 0;
        int j = 0;
#pragma unroll 4
        for (; j + 1 < m; j += 2) {
            int s0 = __shfl_sync(0xffffffffu, id, j);
            int s1 = __shfl_sync(0xffffffffu, id, j + 1);
            aA += G[(size_t)s0 * 32 + lane];
            aB += G[(size_t)s1 * 32 + lane];
        }
        if (j < m) {
            int s0 = __shfl_sync(0xffffffffu, id, j);
            aA += G[(size_t)s0 * 32 + lane];
        }
    }
    float v = (aA + aB) * g_dinv[row] + b3[lane];
    float ss = v * v;
#pragma unroll
    for (int o = 16; o; o >>= 1) ss += __shfl_xor_sync(0xffffffffu, ss, o);
    float nrm = sqrtf(ss);
    out[(size_t)row * 32 + lane] = v / fmaxf(nrm, 1e-12f);
}

// ---------------- launcher ---------------------------------------------------
extern "C" void kernel_launch(void* const* d_in, const int* in_sizes, int n_in,
                              void* d_out, int out_size)
{
    const float* x     = (const float*)d_in[0];
    const int*   ei    = (const int*)  d_in[1];
    const float* W_pre = (const float*)d_in[2];
    const float* b_pre = (const float*)d_in[3];
    const float* W1    = (const float*)d_in[4];
    const float* b1    = (const float*)d_in[5];
    const float* W2    = (const float*)d_in[6];
    const float* b2    = (const float*)d_in[7];
    const float* W3    = (const float*)d_in[8];
    const float* b3    = (const float*)d_in[9];
    float* out = (float*)d_out;

    const int n = in_sizes[0] / 128;
    const int E = in_sizes[1] / 2;

    float *pH, *pG, *pA;
    cudaGetSymbolAddress((void**)&pH, g_H);
    cudaGetSymbolAddress((void**)&pG, g_G);
    cudaGetSymbolAddress((void**)&pA, g_A);

    const int nb  = (n + 255) / 256;
    const int eb  = (E + 255) / 256;
    const int gb  = (n + 127) / 128;   // ROWS=128 for all GEMM shapes
    const int wb  = (n + 7) / 8;

    // ---- CSR build (reused by all 3 convs) ----
    zero_k<<<nb, 256>>>(ei, n);
    deg_accum_k<<<eb, 256>>>(ei, E);
    scan1_k<<<nb, 256>>>(n);
    scan23_k<<<nb, 512>>>(n, nb, E);
    fill_k<<<eb, 256>>>(ei, E);

    // ---- network ----
    gemm_k<128, 64, false, false><<<gb, 128>>>(x, W_pre, nullptr, b_pre, pH, n);

    gemm_k<64, 64, false, true><<<gb, 128>>>(pH, W1, nullptr, nullptr, pG, n);
    gather64_k<<<wb, 256>>>(pG, pA, n);

    gemm_k<64, 64, true, true><<<gb, 128>>>(pA, W2, b1, nullptr, pG, n);
    gather64_k<<<wb, 256>>>(pG, pA, n);

    gemm_k<64, 32, true, true><<<gb, 128>>>(pA, W3, b2, nullptr, pG, n);
    gather_final_k<<<wb, 256>>>(pG, b3, out, n);
}

// round 7
// speedup vs baseline: 1.0009x; 1.0008x over previous
#include <cuda_runtime.h>
#include <cstdint>
#include <cstddef>

#define NMAX 100000
#define EMAX 1700000

// ---------------- scratch (device globals; no allocations allowed) ----------
__device__ float g_H[(size_t)NMAX * 64];
__device__ float g_G[(size_t)NMAX * 64];
__device__ float g_A[(size_t)NMAX * 64];
__device__ float g_dinv[NMAX];
__device__ int   g_deg[NMAX];
__device__ int   g_fill[NMAX];
__device__ int   g_rowptr[NMAX + 1];
__device__ int   g_bsum[1024];
__device__ int   g_csr[EMAX];
__device__ int   g_is64;

typedef unsigned long long ull;

// f32x2 packed FMA (sm_100+): d = a*b + d, lanewise on 2 packed fp32
__device__ __forceinline__ void fma2(ull& d, ull a, ull b) {
    asm("fma.rn.f32x2 %0, %1, %2, %0;" : "+l"(d) : "l"(a), "l"(b));
}
__device__ __forceinline__ float2 unpk(ull a) {
    float2 v;
    asm("mov.b64 {%0, %1}, %2;" : "=f"(v.x), "=f"(v.y) : "l"(a));
    return v;
}

// ---------------- zero + edge dtype detection --------------------------------
__global__ void zero_k(const int* __restrict__ ei, int n) {
    int i = blockIdx.x * 256 + threadIdx.x;
    if (i < n) { g_deg[i] = 0; g_fill[i] = 0; }
    if (blockIdx.x == 0 && threadIdx.x == 0) {
        // int64 little-endian, values < 2^31 => odd 32-bit words all zero
        int ok = 1;
        for (int j = 0; j < 64; j++)
            if (ei[2 * j + 1] != 0) { ok = 0; break; }
        g_is64 = ok;
    }
}

// ---------------- CSR build --------------------------------------------------
__global__ void deg_accum_k(const int* __restrict__ ei, int E) {
    int e = blockIdx.x * 256 + threadIdx.x;
    if (e >= E) return;
    int d;
    if (g_is64) d = ((const int2*)ei)[(size_t)E + e].x;
    else        d = ei[(size_t)E + e];
    atomicAdd(&g_deg[d], 1);
}

__global__ void scan1_k(int n) {
    __shared__ int s[256];
    int tx = threadIdx.x;
    int i = blockIdx.x * 256 + tx;
    int v = (i < n) ? g_deg[i] : 0;
    s[tx] = v;
    __syncthreads();
#pragma unroll
    for (int o = 1; o < 256; o <<= 1) {
        int t = 0;
        if (tx >= o) t = s[tx - o];
        __syncthreads();
        if (tx >= o) s[tx] += t;
        __syncthreads();
    }
    if (i < n) g_rowptr[i] = s[tx] - v;
    if (tx == 255) g_bsum[blockIdx.x] = s[255];
}

// merged: block-offset scan (redundant per block) + apply + dinv
__global__ void scan23_k(int n, int nb, int E) {
    __shared__ int s[512];
    int tx = threadIdx.x;
    int v = (tx < nb) ? g_bsum[tx] : 0;
    s[tx] = v;
    __syncthreads();
#pragma unroll
    for (int o = 1; o < 512; o <<= 1) {
        int t = 0;
        if (tx >= o) t = s[tx - o];
        __syncthreads();
        if (tx >= o) s[tx] += t;
        __syncthreads();
    }
    int prefix = (blockIdx.x == 0) ? 0 : s[blockIdx.x - 1];   // inclusive scan -> excl
    if (tx < 256) {
        int i = blockIdx.x * 256 + tx;
        if (i < n) {
            g_rowptr[i] += prefix;
            g_dinv[i] = rsqrtf((float)(g_deg[i] + 1));
        }
    }
    if (blockIdx.x == 0 && tx == 0) g_rowptr[n] = E;
}

__global__ void fill_k(const int* __restrict__ ei, int E) {
    int e = blockIdx.x * 256 + threadIdx.x;
    if (e >= E) return;
    int s, d;
    if (g_is64) {
        s = ((const int2*)ei)[e].x;
        d = ((const int2*)ei)[(size_t)E + e].x;
    } else {
        s = ei[e];
        d = ei[(size_t)E + e];
    }
    int pos = g_rowptr[d] + atomicAdd(&g_fill[d], 1);
    g_csr[pos] = s;
}

// ---------------- GEMM with f32x2 FMA, pre-duplicated X ----------------------
// 128 threads/block. RPT rows x 8 cols per thread; ROWS = 128 for all shapes.
// X stored duplicated in smem ({x,x} pairs) so the inner loop needs no packing.
// XOR swizzle by (r>>3) over 16-byte blocks keeps LDS/STS conflict-free.
template <int FIN, int FOUT, bool INTR, bool CONV>
__global__ void __launch_bounds__(128) gemm_k(
    const float* __restrict__ in, const float* __restrict__ W,
    const float* __restrict__ bprev, const float* __restrict__ bout,
    float* __restrict__ out, int n)
{
    constexpr int CG   = FOUT / 8;        // col groups: 8 or 4
    constexpr int RG   = 128 / CG;        // row groups: 16 or 32
    constexpr int RPT  = 128 / RG;        // rows per thread: 8 or 4
    constexpr int ROWS = 128;
    constexpr int KC   = 32;
    constexpr int NC4  = KC / 4;          // input float4 blocks per row (8)
    constexpr int NB   = 2 * NC4;         // duplicated 16B blocks per row (16)

    __shared__ float Xs[ROWS * 2 * KC];   // duplicated: 32 KB
    __shared__ float Ws[KC * FOUT];

    const int tid = threadIdx.x;
    const int r0b = blockIdx.x * ROWS;
    const int rg  = tid / CG;
    const int cg  = tid % CG;
    const int r0  = rg * RPT;
    const int c0  = cg * 8;

    ull acc[RPT][4];
#pragma unroll
    for (int i = 0; i < RPT; i++)
#pragma unroll
        for (int j = 0; j < 4; j++) acc[i][j] = 0ull;

    for (int k0 = 0; k0 < FIN; k0 += KC) {
        // ---- load X tile [ROWS x KC], store duplicated + swizzled ----
        for (int idx = tid; idx < ROWS * NC4; idx += 128) {
            int r  = idx / NC4;
            int c4 = idx % NC4;
            int row = r0b + r;
            int col = k0 + c4 * 4;
            float4 v = make_float4(0.f, 0.f, 0.f, 0.f);
            if (row < n) {
                v = *(const float4*)(in + (size_t)row * FIN + col);
                if (INTR) {
                    float di = g_dinv[row];
                    v.x = fmaxf(fmaf(v.x, di, bprev[col + 0]), 0.f);
                    v.y = fmaxf(fmaf(v.y, di, bprev[col + 1]), 0.f);
                    v.z = fmaxf(fmaf(v.z, di, bprev[col + 2]), 0.f);
                    v.w = fmaxf(fmaf(v.w, di, bprev[col + 3]), 0.f);
                }
            }
            int key = (r >> 3) & (NB - 1);
            int b0 = (2 * c4)     ^ key;
            int b1 = (2 * c4 + 1) ^ key;
            ((float4*)Xs)[r * NB + b0] = make_float4(v.x, v.x, v.y, v.y);
            ((float4*)Xs)[r * NB + b1] = make_float4(v.z, v.z, v.w, v.w);
        }
        // ---- load W chunk [KC x FOUT] ----
        for (int idx = tid; idx < KC * FOUT / 4; idx += 128)
            ((float4*)Ws)[idx] = ((const float4*)(W + (size_t)k0 * FOUT))[idx];
        __syncthreads();

        // ---- inner loop: 4 k per step ----
#pragma unroll
        for (int kk = 0; kk < KC; kk += 4) {
            ulonglong2 w[4][2];
#pragma unroll
            for (int kj = 0; kj < 4; kj++) {
                const float* wr = Ws + (kk + kj) * FOUT + c0;
                w[kj][0] = *(const ulonglong2*)(wr);
                w[kj][1] = *(const ulonglong2*)(wr + 4);
            }
#pragma unroll
            for (int i = 0; i < RPT; i++) {
                int r = r0 + i;
                int key = (r >> 3) & (NB - 1);
                int bA = ((kk >> 1))     ^ key;
                int bB = ((kk >> 1) + 1) ^ key;
                ulonglong2 pA = ((const ulonglong2*)Xs)[r * NB + bA]; // {x0,x0},{x1,x1}
                ulonglong2 pB = ((const ulonglong2*)Xs)[r * NB + bB]; // {x2,x2},{x3,x3}
                fma2(acc[i][0], pA.x, w[0][0].x);
                fma2(acc[i][1], pA.x, w[0][0].y);
                fma2(acc[i][2], pA.x, w[0][1].x);
                fma2(acc[i][3], pA.x, w[0][1].y);
                fma2(acc[i][0], pA.y, w[1][0].x);
                fma2(acc[i][1], pA.y, w[1][0].y);
                fma2(acc[i][2], pA.y, w[1][1].x);
                fma2(acc[i][3], pA.y, w[1][1].y);
                fma2(acc[i][0], pB.x, w[2][0].x);
                fma2(acc[i][1], pB.x, w[2][0].y);
                fma2(acc[i][2], pB.x, w[2][1].x);
                fma2(acc[i][3], pB.x, w[2][1].y);
                fma2(acc[i][0], pB.y, w[3][0].x);
                fma2(acc[i][1], pB.y, w[3][0].y);
                fma2(acc[i][2], pB.y, w[3][1].x);
                fma2(acc[i][3], pB.y, w[3][1].y);
            }
        }
        __syncthreads();
    }

    // ---- epilogue ----
#pragma unroll
    for (int i = 0; i < RPT; i++) {
        int row = r0b + r0 + i;
        if (row < n) {
            float v[8];
#pragma unroll
            for (int j = 0; j < 4; j++) {
                float2 p = unpk(acc[i][j]);
                v[2 * j] = p.x; v[2 * j + 1] = p.y;
            }
            if (CONV) {
                float di = g_dinv[row];
#pragma unroll
                for (int j = 0; j < 8; j++) v[j] *= di;
            } else {
#pragma unroll
                for (int j = 0; j < 8; j++) v[j] += bout[c0 + j];
            }
            float* o = out + (size_t)row * FOUT + c0;
            *(float4*)(o)     = make_float4(v[0], v[1], v[2], v[3]);
            *(float4*)(o + 4) = make_float4(v[4], v[5], v[6], v[7]);
        }
    }
}

// ---------------- gather (64 cols): A[dst] = G[dst] + sum G[src] -------------
__global__ void gather64_k(const float* __restrict__ G, float* __restrict__ A, int n)
{
    int row  = blockIdx.x * 8 + (threadIdx.x >> 5);
    int lane = threadIdx.x & 31;
    if (row >= n) return;                        // warp-uniform exit
    const float2* G2 = (const float2*)G;
    int beg = g_rowptr[row], end = g_rowptr[row + 1];
    float2 aA = G2[(size_t)row * 32 + lane];     // self-loop term
    float2 aB = make_float2(0.f, 0.f);
    for (int p = beg; p < end; p += 32) {
        int m = end - p;
        if (m > 32) m = 32;
        int id = (lane < m) ? g_csr[p + lane] : 0;
        int j = 0;
#pragma unroll 4
        for (; j + 1 < m; j += 2) {
            int s0 = __shfl_sync(0xffffffffu, id, j);
            int s1 = __shfl_sync(0xffffffffu, id, j + 1);
            float2 v0 = G2[(size_t)s0 * 32 + lane];
            float2 v1 = G2[(size_t)s1 * 32 + lane];
            aA.x += v0.x; aA.y += v0.y;
            aB.x += v1.x; aB.y += v1.y;
        }
        if (j < m) {
            int s0 = __shfl_sync(0xffffffffu, id, j);
            float2 v0 = G2[(size_t)s0 * 32 + lane];
            aA.x += v0.x; aA.y += v0.y;
        }
    }
    ((float2*)A)[(size_t)row * 32 + lane] = make_float2(aA.x + aB.x, aA.y + aB.y);
}

// ---------------- fused gather (32 cols) + L2 normalize ----------------------
__global__ void gather_final_k(const float* __restrict__ G, const float* __restrict__ b3,
                               float* __restrict__ out, int n)
{
    int row  = blockIdx.x * 8 + (threadIdx.x >> 5);
    int lane = threadIdx.x & 31;
    if (row >= n) return;
    int beg = g_rowptr[row], end = g_rowptr[row + 1];
    float aA = G[(size_t)row * 32 + lane];
    float aB = 0.f;
    for (int p = beg; p < end; p += 32) {
        int m = end - p;
        if (m > 32) m = 32;
        int id = (lane < m) ? g_csr[p + lane] : 0;
        int j = 0;
#pragma unroll 4
        for (; j + 1 < m; j += 2) {
            int s0 = __shfl_sync(0xffffffffu, id, j);
            int s1 = __shfl_sync(0xffffffffu, id, j + 1);
            aA += G[(size_t)s0 * 32 + lane];
            aB += G[(size_t)s1 * 32 + lane];
        }
        if (j < m) {
            int s0 = __shfl_sync(0xffffffffu, id, j);
            aA += G[(size_t)s0 * 32 + lane];
        }
    }
    float v = (aA + aB) * g_dinv[row] + b3[lane];
    float ss = v * v;
#pragma unroll
    for (int o = 16; o; o >>= 1) ss += __shfl_xor_sync(0xffffffffu, ss, o);
    float nrm = sqrtf(ss);
    out[(size_t)row * 32 + lane] = v / fmaxf(nrm, 1e-12f);
}

// ---------------- launcher ---------------------------------------------------
extern "C" void kernel_launch(void* const* d_in, const int* in_sizes, int n_in,
                              void* d_out, int out_size)
{
    const float* x     = (const float*)d_in[0];
    const int*   ei    = (const int*)  d_in[1];
    const float* W_pre = (const float*)d_in[2];
    const float* b_pre = (const float*)d_in[3];
    const float* W1    = (const float*)d_in[4];
    const float* b1    = (const float*)d_in[5];
    const float* W2    = (const float*)d_in[6];
    const float* b2    = (const float*)d_in[7];
    const float* W3    = (const float*)d_in[8];
    const float* b3    = (const float*)d_in[9];
    float* out = (float*)d_out;

    const int n = in_sizes[0] / 128;
    const int E = in_sizes[1] / 2;

    float *pH, *pG, *pA;
    cudaGetSymbolAddress((void**)&pH, g_H);
    cudaGetSymbolAddress((void**)&pG, g_G);
    cudaGetSymbolAddress((void**)&pA, g_A);

    const int nb  = (n + 255) / 256;
    const int eb  = (E + 255) / 256;
    const int gb  = (n + 127) / 128;   // ROWS=128 for all GEMM shapes
    const int wb  = (n + 7) / 8;

    // ---- CSR build (reused by all 3 convs) ----
    zero_k<<<nb, 256>>>(ei, n);
    deg_accum_k<<<eb, 256>>>(ei, E);
    scan1_k<<<nb, 256>>>(n);
    scan23_k<<<nb, 512>>>(n, nb, E);
    fill_k<<<eb, 256>>>(ei, E);

    // ---- network ----
    gemm_k<128, 64, false, false><<<gb, 128>>>(x, W_pre, nullptr, b_pre, pH, n);

    gemm_k<64, 64, false, true><<<gb, 128>>>(pH, W1, nullptr, nullptr, pG, n);
    gather64_k<<<wb, 256>>>(pG, pA, n);

    gemm_k<64, 64, true, true><<<gb, 128>>>(pA, W2, b1, nullptr, pG, n);
    gather64_k<<<wb, 256>>>(pG, pA, n);

    gemm_k<64, 32, true, true><<<gb, 128>>>(pA, W3, b2, nullptr, pG, n);
    gather_final_k<<<wb, 256>>>(pG, b3, out, n);
}